// round 2
// baseline (speedup 1.0000x reference)
#include <cuda_runtime.h>
#include <math.h>

// Problem constants
#define B_   2
#define S_   2048
#define E_   2048
#define HQ_  32
#define HKV_ 8
#define D_   64
#define KVD_ 512   // HKV_*D_

// Scratch (static device arrays: allocation-free rule)
__device__ float g_Q[(size_t)B_*S_*E_];     // 33.5 MB
__device__ float g_K[(size_t)B_*S_*KVD_];   //  8.4 MB
__device__ float g_V[(size_t)B_*S_*KVD_];   //  8.4 MB
__device__ float g_C[(size_t)B_*S_*E_];     // 33.5 MB (attention context, pre-Wo)

// ---------------------------------------------------------------------------
// SGEMM: C[M,N] = A[M,K] @ B[K,N] + bias[N]
// Classic 128x128x8 tile, 256 threads, 8x8 microtile, float4 loads.
// All dims are multiples of tile sizes for this problem (M=4096, N in {512,2048}, K=2048).
// ---------------------------------------------------------------------------
#define BM 128
#define BN 128
#define BK 8
__global__ __launch_bounds__(256) void sgemm_bias(
    int M, int N, int K,
    const float* __restrict__ A, const float* __restrict__ Bm,
    const float* __restrict__ bias, float* __restrict__ C)
{
    __shared__ float As[BK][BM];
    __shared__ float Bs[BK][BN];

    const int t = threadIdx.x;
    const int cCol = blockIdx.x;   // N tile
    const int cRow = blockIdx.y;   // M tile

    A  += (size_t)cRow * BM * K;
    Bm += (size_t)cCol * BN;
    C  += (size_t)cRow * BM * N + (size_t)cCol * BN;
    const float* biasp = bias + (size_t)cCol * BN;

    const int aRow = t >> 1;          // 0..127
    const int aCol = (t & 1) * 4;     // 0 or 4
    const int bRow = t >> 5;          // 0..7
    const int bCol = (t & 31) * 4;    // 0..124

    const int tx = t & 15;            // 16 col groups
    const int ty = t >> 4;            // 16 row groups

    float acc[8][8];
    #pragma unroll
    for (int i = 0; i < 8; ++i)
        #pragma unroll
        for (int j = 0; j < 8; ++j) acc[i][j] = 0.f;

    for (int k0 = 0; k0 < K; k0 += BK) {
        float4 a4 = *(const float4*)(A + (size_t)aRow * K + aCol);
        As[aCol + 0][aRow] = a4.x;
        As[aCol + 1][aRow] = a4.y;
        As[aCol + 2][aRow] = a4.z;
        As[aCol + 3][aRow] = a4.w;
        *(float4*)(&Bs[bRow][bCol]) = *(const float4*)(Bm + (size_t)bRow * N + bCol);
        __syncthreads();

        A  += BK;
        Bm += (size_t)BK * N;

        #pragma unroll
        for (int k = 0; k < BK; ++k) {
            float4 m0 = *(float4*)(&As[k][ty * 8]);
            float4 m1 = *(float4*)(&As[k][ty * 8 + 4]);
            float4 n0 = *(float4*)(&Bs[k][tx * 8]);
            float4 n1 = *(float4*)(&Bs[k][tx * 8 + 4]);
            float rm[8] = {m0.x, m0.y, m0.z, m0.w, m1.x, m1.y, m1.z, m1.w};
            float rn[8] = {n0.x, n0.y, n0.z, n0.w, n1.x, n1.y, n1.z, n1.w};
            #pragma unroll
            for (int i = 0; i < 8; ++i)
                #pragma unroll
                for (int j = 0; j < 8; ++j)
                    acc[i][j] += rm[i] * rn[j];
        }
        __syncthreads();
    }

    #pragma unroll
    for (int i = 0; i < 8; ++i) {
        float* crow = C + (size_t)(ty * 8 + i) * N + tx * 8;
        #pragma unroll
        for (int j = 0; j < 8; ++j)
            crow[j] = acc[i][j] + biasp[tx * 8 + j];
    }
}

// ---------------------------------------------------------------------------
// GQA attention: one block = 16 query rows of one (batch, q-head).
// Full 16x2048 score panel held in SMEM; softmax in place; attn weights
// written to global exactly once; context accumulated from SMEM P.
// ---------------------------------------------------------------------------
#define QT 16
#define KT 64
#define KVPAD 65   // row pad (floats) for K/V smem tile

// smem floats: sQ 16*64, sKV 64*65, sS 16*2048, sInv/sTmp 32
#define ATT_SMEM_FLOATS (QT*D_ + KT*KVPAD + QT*S_ + 32)
#define ATT_SMEM_BYTES  (ATT_SMEM_FLOATS * 4)

__global__ __launch_bounds__(256) void gqa_attn(
    const float* __restrict__ Qb, const float* __restrict__ Kb,
    const float* __restrict__ Vb, float* __restrict__ Cb,
    float* __restrict__ attn)
{
    extern __shared__ float sm[];
    float* sQ   = sm;                       // QT*D_
    float* sKV  = sQ  + QT * D_;            // KT*KVPAD
    float* sS   = sKV + KT * KVPAD;         // QT*S_
    float* sInv = sS  + QT * S_;            // QT

    const int t  = threadIdx.x;
    const int qi = t >> 4;                  // 0..15: q row
    const int c  = t & 15;                  // 0..15: lane within row group
    const int q0 = blockIdx.x * QT;
    const int h  = blockIdx.y;
    const int b  = blockIdx.z;
    const int hkv = h >> 2;
    const float scale = 0.125f;             // 1/sqrt(64)

    const float* Qg = Qb + ((size_t)b * S_ + q0) * E_ + h * D_;
    const float* Kg = Kb + (size_t)b * S_ * KVD_ + hkv * D_;
    const float* Vg = Vb + (size_t)b * S_ * KVD_ + hkv * D_;

    // load Q tile (16x64)
    for (int e = t; e < QT * D_; e += 256)
        sQ[e] = Qg[(size_t)(e >> 6) * E_ + (e & 63)];

    // ---- Phase 1: scores = scale * Q K^T, into sS ----
    for (int kt = 0; kt < S_ / KT; ++kt) {
        __syncthreads();
        for (int e = t; e < KT * D_; e += 256) {
            int kr = e >> 6, d = e & 63;
            sKV[kr * KVPAD + d] = Kg[(size_t)(kt * KT + kr) * KVD_ + d];
        }
        __syncthreads();
        float a0 = 0.f, a1 = 0.f, a2 = 0.f, a3 = 0.f;
        const float* qrow = sQ + qi * D_;
        #pragma unroll 16
        for (int d = 0; d < D_; ++d) {
            float qv = qrow[d];
            a0 += qv * sKV[(c     ) * KVPAD + d];
            a1 += qv * sKV[(c + 16) * KVPAD + d];
            a2 += qv * sKV[(c + 32) * KVPAD + d];
            a3 += qv * sKV[(c + 48) * KVPAD + d];
        }
        float* srow = sS + (size_t)qi * S_ + kt * KT + c;
        srow[0]  = a0 * scale;
        srow[16] = a1 * scale;
        srow[32] = a2 * scale;
        srow[48] = a3 * scale;
    }
    __syncthreads();

    // ---- Phase 2a: row max ----
    float mx = -1e30f;
    {
        const float* srow = sS + (size_t)qi * S_;
        for (int k = c; k < S_; k += 16) mx = fmaxf(mx, srow[k]);
        #pragma unroll
        for (int o = 8; o; o >>= 1)
            mx = fmaxf(mx, __shfl_xor_sync(0xffffffffu, mx, o));
    }

    // ---- Phase 2b: exp + sum (P kept unnormalized in sS) ----
    float ssum = 0.f;
    {
        float* srow = sS + (size_t)qi * S_;
        for (int k = c; k < S_; k += 16) {
            float p = __expf(srow[k] - mx);
            srow[k] = p;
            ssum += p;
        }
        #pragma unroll
        for (int o = 8; o; o >>= 1)
            ssum += __shfl_xor_sync(0xffffffffu, ssum, o);
        if (c == 0) sInv[qi] = 1.0f / ssum;
    }
    __syncthreads();

    // ---- Phase 2c: write normalized attn weights ----
    if (attn) {
        float* ag = attn + (((size_t)(b * HQ_ + h)) * S_ + q0) * S_;
        for (int idx = t; idx < QT * S_; idx += 256) {
            int r = idx >> 11;            // S_ = 2048
            int k = idx & (S_ - 1);
            ag[(size_t)r * S_ + k] = sS[(size_t)r * S_ + k] * sInv[r];
        }
    }

    // ---- Phase 2d: context = (P @ V) / sum ----
    const int d4 = c * 4;
    float o0 = 0.f, o1 = 0.f, o2 = 0.f, o3 = 0.f;
    for (int kt = 0; kt < S_ / KT; ++kt) {
        __syncthreads();
        for (int e = t; e < KT * D_; e += 256) {
            int kr = e >> 6, d = e & 63;
            sKV[kr * KVPAD + d] = Vg[(size_t)(kt * KT + kr) * KVD_ + d];
        }
        __syncthreads();
        const float* prow = sS + (size_t)qi * S_ + kt * KT;
        #pragma unroll 8
        for (int k = 0; k < KT; ++k) {
            float p = prow[k];
            const float* vrow = sKV + k * KVPAD + d4;
            o0 += p * vrow[0];
            o1 += p * vrow[1];
            o2 += p * vrow[2];
            o3 += p * vrow[3];
        }
    }
    float inv = sInv[qi];
    float* cg = Cb + ((size_t)b * S_ + q0 + qi) * E_ + h * D_ + d4;
    cg[0] = o0 * inv;
    cg[1] = o1 * inv;
    cg[2] = o2 * inv;
    cg[3] = o3 * inv;
}

// ---------------------------------------------------------------------------
extern "C" void kernel_launch(void* const* d_in, const int* in_sizes, int n_in,
                              void* d_out, int out_size)
{
    const float* query = (const float*)d_in[0];
    const float* key   = (const float*)d_in[1];
    const float* value = (const float*)d_in[2];
    const float* Wq = (const float*)d_in[3];
    const float* bq = (const float*)d_in[4];
    const float* Wk = (const float*)d_in[5];
    const float* bk = (const float*)d_in[6];
    const float* Wv = (const float*)d_in[7];
    const float* bv = (const float*)d_in[8];
    const float* Wo = (const float*)d_in[9];
    const float* bo = (const float*)d_in[10];
    float* out = (float*)d_out;

    float *qbuf, *kbuf, *vbuf, *cbuf;
    cudaGetSymbolAddress((void**)&qbuf, g_Q);
    cudaGetSymbolAddress((void**)&kbuf, g_K);
    cudaGetSymbolAddress((void**)&vbuf, g_V);
    cudaGetSymbolAddress((void**)&cbuf, g_C);

    const int M = B_ * S_;   // 4096
    dim3 blk(256);

    // Projections
    sgemm_bias<<<dim3(E_ / BN, M / BM), blk>>>(M, E_,   E_, query, Wq, bq, qbuf);
    sgemm_bias<<<dim3(KVD_ / BN, M / BM), blk>>>(M, KVD_, E_, key,   Wk, bk, kbuf);
    sgemm_bias<<<dim3(KVD_ / BN, M / BM), blk>>>(M, KVD_, E_, value, Wv, bv, vbuf);

    // Attention (+ optional attn-weights output as second tensor)
    const size_t main_elems = (size_t)B_ * S_ * E_;    // 8388608
    float* attn = ((size_t)out_size > main_elems) ? (out + main_elems) : nullptr;

    cudaFuncSetAttribute(gqa_attn, cudaFuncAttributeMaxDynamicSharedMemorySize,
                         ATT_SMEM_BYTES);
    gqa_attn<<<dim3(S_ / QT, HQ_, B_), blk, ATT_SMEM_BYTES>>>(qbuf, kbuf, vbuf,
                                                              cbuf, attn);

    // Output projection
    sgemm_bias<<<dim3(E_ / BN, M / BM), blk>>>(M, E_, E_, cbuf, Wo, bo, out);
}

// round 3
// speedup vs baseline: 5.4171x; 5.4171x over previous
#include <cuda_runtime.h>
#include <math.h>

// Problem constants
#define B_   2
#define S_   2048
#define E_   2048
#define HQ_  32
#define HKV_ 8
#define D_   64
#define KVD_ 512

// Scratch (static device arrays: allocation-free rule)
__device__ float g_Q[(size_t)B_*S_*E_];     // 33.5 MB
__device__ float g_K[(size_t)B_*S_*KVD_];   //  8.4 MB
__device__ float g_V[(size_t)B_*S_*KVD_];   //  8.4 MB
__device__ float g_C[(size_t)B_*S_*E_];     // 33.5 MB (attention context, pre-Wo)

// ---------------------------------------------------------------------------
// TF32 helpers
// ---------------------------------------------------------------------------
__device__ __forceinline__ unsigned f2tf(float f) {
    unsigned r;
    asm("cvt.rna.tf32.f32 %0, %1;" : "=r"(r) : "f"(f));
    return r;
}

__device__ __forceinline__ void mma_tf32(float c[4],
                                         unsigned a0, unsigned a1, unsigned a2, unsigned a3,
                                         unsigned b0, unsigned b1) {
    asm volatile(
        "mma.sync.aligned.m16n8k8.row.col.f32.tf32.tf32.f32 "
        "{%0,%1,%2,%3},{%4,%5,%6,%7},{%8,%9},{%0,%1,%2,%3};"
        : "+f"(c[0]), "+f"(c[1]), "+f"(c[2]), "+f"(c[3])
        : "r"(a0), "r"(a1), "r"(a2), "r"(a3), "r"(b0), "r"(b1));
}

// ---------------------------------------------------------------------------
// Generic TF32 tensor-core GEMM:  C = alpha * A @ op(B) + bias
//   A: M x K row-major (lda)
//   B: NT=false -> K x N row-major (ldb);  NT=true -> N x K row-major (ldb)
//   C: M x N row-major (ldc)
// Block tile BM x BN x 16, warp tile 64x32, mma m16n8k8.
// mode 0: plain.  mode 1: scores (A=Q slice, B=K slice, C=attn panel).
// mode 2: PV (A=attn panel, B=V slice, C=context slice).
// All dims must divide tiles exactly (true for every call below).
// ---------------------------------------------------------------------------
#define BKK 16

template<int BM, int BN, bool NT>
__global__ void __launch_bounds__((BM/64)*(BN/32)*32) mm_tf32(
    int M, int N, int K,
    const float* __restrict__ A, int lda,
    const float* __restrict__ Bm, int ldb,
    float* __restrict__ C, int ldc,
    const float* __restrict__ bias, float alpha, int mode)
{
    constexpr int WM_ = BM / 64;
    constexpr int WN_ = BN / 32;
    constexpr int NTH = WM_ * WN_ * 32;

    __shared__ unsigned As[BKK * BM];
    __shared__ unsigned Bs[BKK * BN];

    const int t    = threadIdx.x;
    const int w    = t >> 5;
    const int lane = t & 31;
    const int wm   = w % WM_;
    const int wn   = w / WM_;
    const int m0   = blockIdx.y * BM;
    const int n0   = blockIdx.x * BN;

    if (mode == 1) {                 // scores: per (b,h) batch
        int bh = blockIdx.z, b = bh >> 5, h = bh & 31;
        A  += (size_t)b * S_ * E_ + (size_t)h * D_;
        Bm += (size_t)b * S_ * KVD_ + (size_t)(h >> 2) * D_;
        C  += (size_t)bh * S_ * S_;
    } else if (mode == 2) {          // PV
        int bh = blockIdx.z, b = bh >> 5, h = bh & 31;
        A  += (size_t)bh * S_ * S_;
        Bm += (size_t)b * S_ * KVD_ + (size_t)(h >> 2) * D_;
        C  += (size_t)b * S_ * E_ + (size_t)h * D_;
    }

    float acc[4][4][4];
    #pragma unroll
    for (int i = 0; i < 4; ++i)
        #pragma unroll
        for (int j = 0; j < 4; ++j)
            #pragma unroll
            for (int r = 0; r < 4; ++r) acc[i][j][r] = 0.f;

    const unsigned sw = (lane & 3) << 3;   // fragment-load swizzle constant

    for (int k0 = 0; k0 < K; k0 += BKK) {
        // ---- stage A (always row-major M x K): float4 along k, swizzled scatter ----
        #pragma unroll
        for (int idx = t; idx < BM * BKK / 4; idx += NTH) {
            int quad = idx & 3;           // BKK/4 = 4
            int m    = idx >> 2;
            float4 v = *(const float4*)(A + (size_t)(m0 + m) * lda + k0 + quad * 4);
            int kb = quad * 4;
            As[(kb + 0) * BM + (m ^ 0 )] = f2tf(v.x);
            As[(kb + 1) * BM + (m ^ 8 )] = f2tf(v.y);
            As[(kb + 2) * BM + (m ^ 16)] = f2tf(v.z);
            As[(kb + 3) * BM + (m ^ 24)] = f2tf(v.w);
        }
        // ---- stage B ----
        if (!NT) {   // B is K x N: float4 along n, vectorized swizzled store
            #pragma unroll
            for (int idx = t; idx < BKK * BN / 4; idx += NTH) {
                int nq = idx % (BN / 4);
                int k  = idx / (BN / 4);
                float4 v = *(const float4*)(Bm + (size_t)(k0 + k) * ldb + n0 + nq * 4);
                unsigned c = (k & 3) << 3;
                unsigned* dst = &Bs[k * BN + ((nq * 4) ^ c)];
                dst[0] = f2tf(v.x); dst[1] = f2tf(v.y);
                dst[2] = f2tf(v.z); dst[3] = f2tf(v.w);
            }
        } else {     // B is N x K: float4 along k, swizzled scatter
            #pragma unroll
            for (int idx = t; idx < BN * BKK / 4; idx += NTH) {
                int quad = idx & 3;
                int n    = idx >> 2;
                float4 v = *(const float4*)(Bm + (size_t)(n0 + n) * ldb + k0 + quad * 4);
                int kb = quad * 4;
                Bs[(kb + 0) * BN + (n ^ 0 )] = f2tf(v.x);
                Bs[(kb + 1) * BN + (n ^ 8 )] = f2tf(v.y);
                Bs[(kb + 2) * BN + (n ^ 16)] = f2tf(v.z);
                Bs[(kb + 3) * BN + (n ^ 24)] = f2tf(v.w);
            }
        }
        __syncthreads();

        // ---- compute: 2 k8-steps ----
        #pragma unroll
        for (int ks = 0; ks < BKK / 8; ++ks) {
            const int kb  = ks * 8;
            const int kk  = kb + (lane & 3);
            const int kk2 = kk + 4;

            unsigned af[4][4];
            #pragma unroll
            for (int mi = 0; mi < 4; ++mi) {
                int r = wm * 64 + mi * 16 + (lane >> 2);
                af[mi][0] = As[kk  * BM + ( r      ^ sw)];
                af[mi][1] = As[kk  * BM + ((r + 8) ^ sw)];
                af[mi][2] = As[kk2 * BM + ( r      ^ sw)];
                af[mi][3] = As[kk2 * BM + ((r + 8) ^ sw)];
            }
            unsigned bf[4][2];
            #pragma unroll
            for (int ni = 0; ni < 4; ++ni) {
                int n = wn * 32 + ni * 8 + (lane >> 2);
                bf[ni][0] = Bs[kk  * BN + (n ^ sw)];
                bf[ni][1] = Bs[kk2 * BN + (n ^ sw)];
            }
            #pragma unroll
            for (int mi = 0; mi < 4; ++mi)
                #pragma unroll
                for (int ni = 0; ni < 4; ++ni)
                    mma_tf32(acc[mi][ni], af[mi][0], af[mi][1], af[mi][2], af[mi][3],
                             bf[ni][0], bf[ni][1]);
        }
        __syncthreads();
    }

    // ---- epilogue ----
    #pragma unroll
    for (int mi = 0; mi < 4; ++mi) {
        int r0 = m0 + wm * 64 + mi * 16 + (lane >> 2);
        int r1 = r0 + 8;
        #pragma unroll
        for (int ni = 0; ni < 4; ++ni) {
            int cc = n0 + wn * 32 + ni * 8 + 2 * (lane & 3);
            float b0 = 0.f, b1 = 0.f;
            if (bias) { b0 = bias[cc]; b1 = bias[cc + 1]; }
            float2 v0 = { alpha * acc[mi][ni][0] + b0, alpha * acc[mi][ni][1] + b1 };
            float2 v1 = { alpha * acc[mi][ni][2] + b0, alpha * acc[mi][ni][3] + b1 };
            *(float2*)(C + (size_t)r0 * ldc + cc) = v0;
            *(float2*)(C + (size_t)r1 * ldc + cc) = v1;
        }
    }
}

// ---------------------------------------------------------------------------
// Row softmax, in place. One block per row of 2048 floats.
// ---------------------------------------------------------------------------
__global__ __launch_bounds__(256) void softmax_rows(float* __restrict__ attn)
{
    __shared__ float red_m[8];
    __shared__ float red_s[8];

    const size_t row = blockIdx.x;
    float4* p = (float4*)(attn + row * (size_t)S_);
    const int t    = threadIdx.x;
    const int lane = t & 31;
    const int wrp  = t >> 5;

    float4 v0 = p[t];
    float4 v1 = p[t + 256];

    float mx = fmaxf(fmaxf(fmaxf(v0.x, v0.y), fmaxf(v0.z, v0.w)),
                     fmaxf(fmaxf(v1.x, v1.y), fmaxf(v1.z, v1.w)));
    #pragma unroll
    for (int o = 16; o; o >>= 1)
        mx = fmaxf(mx, __shfl_xor_sync(0xffffffffu, mx, o));
    if (lane == 0) red_m[wrp] = mx;
    __syncthreads();
    if (t == 0) {
        float m = red_m[0];
        #pragma unroll
        for (int i = 1; i < 8; ++i) m = fmaxf(m, red_m[i]);
        red_m[0] = m;
    }
    __syncthreads();
    mx = red_m[0];

    v0.x = __expf(v0.x - mx); v0.y = __expf(v0.y - mx);
    v0.z = __expf(v0.z - mx); v0.w = __expf(v0.w - mx);
    v1.x = __expf(v1.x - mx); v1.y = __expf(v1.y - mx);
    v1.z = __expf(v1.z - mx); v1.w = __expf(v1.w - mx);

    float s = v0.x + v0.y + v0.z + v0.w + v1.x + v1.y + v1.z + v1.w;
    #pragma unroll
    for (int o = 16; o; o >>= 1)
        s += __shfl_xor_sync(0xffffffffu, s, o);
    if (lane == 0) red_s[wrp] = s;
    __syncthreads();
    if (t == 0) {
        float acc = 0.f;
        #pragma unroll
        for (int i = 0; i < 8; ++i) acc += red_s[i];
        red_s[0] = 1.0f / acc;
    }
    __syncthreads();
    const float inv = red_s[0];

    v0.x *= inv; v0.y *= inv; v0.z *= inv; v0.w *= inv;
    v1.x *= inv; v1.y *= inv; v1.z *= inv; v1.w *= inv;
    p[t]       = v0;
    p[t + 256] = v1;
}

// ---------------------------------------------------------------------------
extern "C" void kernel_launch(void* const* d_in, const int* in_sizes, int n_in,
                              void* d_out, int out_size)
{
    const float* query = (const float*)d_in[0];
    const float* key   = (const float*)d_in[1];
    const float* value = (const float*)d_in[2];
    const float* Wq = (const float*)d_in[3];
    const float* bq = (const float*)d_in[4];
    const float* Wk = (const float*)d_in[5];
    const float* bk = (const float*)d_in[6];
    const float* Wv = (const float*)d_in[7];
    const float* bv = (const float*)d_in[8];
    const float* Wo = (const float*)d_in[9];
    const float* bo = (const float*)d_in[10];
    float* out = (float*)d_out;

    float *qbuf, *kbuf, *vbuf, *cbuf;
    cudaGetSymbolAddress((void**)&qbuf, g_Q);
    cudaGetSymbolAddress((void**)&kbuf, g_K);
    cudaGetSymbolAddress((void**)&vbuf, g_V);
    cudaGetSymbolAddress((void**)&cbuf, g_C);

    const int M = B_ * S_;                       // 4096
    float* attn = out + (size_t)B_ * S_ * E_;    // attn-weights output doubles as score scratch

    // Q/K/V projections (TF32 GEMM, NN)
    mm_tf32<128,128,false><<<dim3(E_/128,  M/128, 1), 256>>>(
        M, E_,   E_, query, E_, Wq, E_,   qbuf, E_,   bq, 1.0f, 0);
    mm_tf32<128,128,false><<<dim3(KVD_/128, M/128, 1), 256>>>(
        M, KVD_, E_, key,   E_, Wk, KVD_, kbuf, KVD_, bk, 1.0f, 0);
    mm_tf32<128,128,false><<<dim3(KVD_/128, M/128, 1), 256>>>(
        M, KVD_, E_, value, E_, Wv, KVD_, vbuf, KVD_, bv, 1.0f, 0);

    // scores = 0.125 * Q K^T  (batched over 64 (b,h) pairs, NT), into attn region
    mm_tf32<128,128,true><<<dim3(S_/128, S_/128, B_*HQ_), 256>>>(
        S_, S_, D_, qbuf, E_, kbuf, KVD_, attn, S_, nullptr, 0.125f, 1);

    // softmax rows in place (this IS the attn-weights output)
    softmax_rows<<<B_*HQ_*S_, 256>>>(attn);

    // context = P @ V  (batched, NN, BN=64)
    mm_tf32<128,64,false><<<dim3(1, S_/128, B_*HQ_), 128>>>(
        S_, D_, S_, attn, S_, vbuf, KVD_, cbuf, E_, nullptr, 1.0f, 2);

    // output projection
    mm_tf32<128,128,false><<<dim3(E_/128, M/128, 1), 256>>>(
        M, E_, E_, cbuf, E_, Wo, E_, out, E_, bo, 1.0f, 0);
}